// round 3
// baseline (speedup 1.0000x reference)
#include <cuda_runtime.h>
#include <math.h>

#define MEM 2048
#define NV4 (MEM / 4)          // float4 per row = 512

// Scratch (allocation-free: __device__ globals)
__device__ float g_sL[MEM];    // w[j] * m_left[j]
__device__ float g_sR[MEM];    // w[j] * m_right[j]
__device__ float g_pL[MEM];    // (ma @ lh)[j]
__device__ float g_pR[MEM];    // (ma @ rh)[j]
__device__ float g_la[MEM];
__device__ float g_ra[MEM];

__device__ __forceinline__ float warp_sum(float v) {
#pragma unroll
    for (int o = 16; o > 0; o >>= 1) v += __shfl_xor_sync(0xffffffffu, v, o);
    return v;
}

__device__ __forceinline__ float dot4(float4 a, float4 b) {
    return fmaf(a.x, b.x, fmaf(a.y, b.y, fmaf(a.z, b.z, a.w * b.w)));
}

// ---------------------------------------------------------------------------
// K1: attention scoring + hoisted ma matvecs.
// 4 rows per block, 12 warps: warp w -> (row = blk*4 + w/3, mat = w%3).
// Vectors lh/rh/S staged in smem; each warp streams one full matrix row
// (16 independent LDG.128) -> high per-warp MLP on the DRAM stream.
// ---------------------------------------------------------------------------
__global__ void __launch_bounds__(384, 3) k1_score(
    const float* __restrict__ lh, const float* __restrict__ rh,
    const float* __restrict__ S,  const float* __restrict__ w,
    const float* __restrict__ Wh_w, const float* __restrict__ Wh_b,
    const float* __restrict__ Us_w, const float* __restrict__ Us_b,
    const float* __restrict__ ma_w)
{
    __shared__ float4 s_lh[NV4];
    __shared__ float4 s_rh[NV4];
    __shared__ float4 s_S[NV4];
    __shared__ float s_res[4][5];   // per row: WL, WR, US, ML, MR

    const int tid  = threadIdx.x;
    const int wid  = tid >> 5;           // 0..11
    const int lane = tid & 31;
    const int r    = wid / 3;            // 0..3 (row within block)
    const int mat  = wid % 3;            // 0=Wh, 1=Us, 2=ma
    const int row  = blockIdx.x * 4 + r;

    // Stage vectors into smem
    const float4* __restrict__ lh4 = (const float4*)lh;
    const float4* __restrict__ rh4 = (const float4*)rh;
    const float4* __restrict__ S4  = (const float4*)S;
    for (int i = tid; i < NV4; i += 384) {
        s_lh[i] = lh4[i];
        s_rh[i] = rh4[i];
        s_S[i]  = S4[i];
    }
    __syncthreads();

    if (mat == 0) {
        const float4* __restrict__ M = (const float4*)Wh_w + (size_t)row * NV4;
        float aL = 0.f, aR = 0.f;
#pragma unroll 8
        for (int i = 0; i < 16; i++) {
            const int idx = i * 32 + lane;
            float4 m = M[idx];
            aL += dot4(m, s_lh[idx]);
            aR += dot4(m, s_rh[idx]);
        }
        aL = warp_sum(aL);
        aR = warp_sum(aR);
        if (lane == 0) { s_res[r][0] = aL; s_res[r][1] = aR; }
    } else if (mat == 1) {
        const float4* __restrict__ M = (const float4*)Us_w + (size_t)row * NV4;
        float aU = 0.f;
#pragma unroll 8
        for (int i = 0; i < 16; i++) {
            const int idx = i * 32 + lane;
            aU += dot4(M[idx], s_S[idx]);
        }
        aU = warp_sum(aU);
        if (lane == 0) s_res[r][2] = aU;
    } else {
        const float4* __restrict__ M = (const float4*)ma_w + (size_t)row * NV4;
        float aL = 0.f, aR = 0.f;
#pragma unroll 8
        for (int i = 0; i < 16; i++) {
            const int idx = i * 32 + lane;
            float4 m = M[idx];
            aL += dot4(m, s_lh[idx]);
            aR += dot4(m, s_rh[idx]);
        }
        aL = warp_sum(aL);
        aR = warp_sum(aR);
        if (lane == 0) { s_res[r][3] = aL; s_res[r][4] = aR; }
    }
    __syncthreads();

    if (tid < 4) {
        const int j = blockIdx.x * 4 + tid;
        const float aWL = s_res[tid][0];
        const float aWR = s_res[tid][1];
        const float aUS = s_res[tid][2];
        const float base = Wh_b[j] + Us_b[j];
        const float mL = tanhf(aWL + aUS + base);
        const float mR = tanhf(aWR + aUS + base);
        const float wj = w[j];
        g_sL[j] = wj * mL;
        g_sR[j] = wj * mR;
        g_pL[j] = s_res[tid][3];
        g_pR[j] = s_res[tid][4];
    }
}

// ---------------------------------------------------------------------------
// K2: reduce scores -> alphas -> la/ra. Single block (tiny).
// ---------------------------------------------------------------------------
__global__ void __launch_bounds__(1024) k2_alpha(const float* __restrict__ ma_b)
{
    __shared__ float sL[1024];
    __shared__ float sR[1024];
    __shared__ float s_aL, s_aR;
    const int t = threadIdx.x;

    sL[t] = g_sL[t] + g_sL[t + 1024];
    sR[t] = g_sR[t] + g_sR[t + 1024];
    __syncthreads();
#pragma unroll
    for (int s = 512; s > 0; s >>= 1) {
        if (t < s) { sL[t] += sL[t + s]; sR[t] += sR[t + s]; }
        __syncthreads();
    }
    if (t == 0) {
        const float eL = sL[0], eR = sR[0];
        const float inv = 1.0f / (eL + eR);
        s_aL = eL * inv;
        s_aR = eR * inv;
    }
    __syncthreads();
    const float aL = s_aL, aR = s_aR;

#pragma unroll
    for (int j = t; j < MEM; j += 1024) {
        const float b = ma_b[j];
        g_la[j] = tanhf(fmaf(aL, g_pL[j], b));
        g_ra[j] = tanhf(fmaf(aR, g_pR[j], b));
    }
}

// ---------------------------------------------------------------------------
// K3: all 8 gate matvecs + LSTM combine.
// 2 rows per block, 16 warps: warp w -> (row = blk*2 + w/8, gate = w%8).
// la/ra staged in smem; each warp streams one full matrix row.
// ---------------------------------------------------------------------------
__global__ void __launch_bounds__(512, 2) k3_gates(
    const float* __restrict__ lc, const float* __restrict__ rc,
    const float* __restrict__ ilh_w,  const float* __restrict__ ilh_b,
    const float* __restrict__ irh_w,  const float* __restrict__ irh_b,
    const float* __restrict__ lflh_w, const float* __restrict__ lflh_b,
    const float* __restrict__ lfrh_w, const float* __restrict__ lfrh_b,
    const float* __restrict__ rflh_w, const float* __restrict__ rflh_b,
    const float* __restrict__ rfrh_w, const float* __restrict__ rfrh_b,
    const float* __restrict__ ulh_w,  const float* __restrict__ ulh_b,
    const float* __restrict__ urh_w,  const float* __restrict__ urh_b,
    float* __restrict__ out)
{
    __shared__ float4 s_la[NV4];
    __shared__ float4 s_ra[NV4];
    __shared__ float s_g[2][8];

    const int tid  = threadIdx.x;
    const int wid  = tid >> 5;        // 0..15
    const int lane = tid & 31;
    const int r    = wid >> 3;        // 0..1
    const int gate = wid & 7;         // 0..7
    const int row  = blockIdx.x * 2 + r;

    const float4* __restrict__ la4 = (const float4*)g_la;
    const float4* __restrict__ ra4 = (const float4*)g_ra;
    for (int i = tid; i < NV4; i += 512) {
        s_la[i] = la4[i];
        s_ra[i] = ra4[i];
    }
    __syncthreads();

    const float* mat;
    switch (gate) {
        case 0: mat = ilh_w;  break;
        case 1: mat = irh_w;  break;
        case 2: mat = lflh_w; break;
        case 3: mat = lfrh_w; break;
        case 4: mat = rflh_w; break;
        case 5: mat = rfrh_w; break;
        case 6: mat = ulh_w;  break;
        default: mat = urh_w; break;
    }
    const float4* __restrict__ M = (const float4*)mat + (size_t)row * NV4;
    const float4* __restrict__ V = (gate & 1) ? s_ra : s_la;

    float acc = 0.f;
#pragma unroll 8
    for (int i = 0; i < 16; i++) {
        const int idx = i * 32 + lane;
        acc += dot4(M[idx], V[idx]);
    }
    acc = warp_sum(acc);
    if (lane == 0) s_g[r][gate] = acc;
    __syncthreads();

    if (tid < 2) {
        const int j = blockIdx.x * 2 + tid;
        const float gi  = s_g[tid][0] + s_g[tid][1] + ilh_b[j]  + irh_b[j];
        const float glf = s_g[tid][2] + s_g[tid][3] + lflh_b[j] + lfrh_b[j];
        const float grf = s_g[tid][4] + s_g[tid][5] + rflh_b[j] + rfrh_b[j];
        const float gu  = s_g[tid][6] + s_g[tid][7] + ulh_b[j]  + urh_b[j];
        const float ig  = 1.0f / (1.0f + expf(-gi));
        const float lf  = 1.0f / (1.0f + expf(-glf));
        const float rf  = 1.0f / (1.0f + expf(-grf));
        const float u   = tanhf(gu);
        const float c   = ig * u + lf * lc[j] + rf * rc[j];
        out[j]       = c;
        out[MEM + j] = tanhf(c);
    }
}

// ---------------------------------------------------------------------------
// Input order (metadata): lc, lh, rc, rh, S, w, then (W, b) pairs for
// Wh, Us, ma, ilh, irh, lflh, lfrh, rflh, rfrh, ulh, urh.
// Output: c (2048 floats) followed by h (2048 floats).
// ---------------------------------------------------------------------------
extern "C" void kernel_launch(void* const* d_in, const int* in_sizes, int n_in,
                              void* d_out, int out_size)
{
    const float* lc = (const float*)d_in[0];
    const float* lh = (const float*)d_in[1];
    const float* rc = (const float*)d_in[2];
    const float* rh = (const float*)d_in[3];
    const float* S  = (const float*)d_in[4];
    const float* w  = (const float*)d_in[5];

    const float* Wh_w   = (const float*)d_in[6];
    const float* Wh_b   = (const float*)d_in[7];
    const float* Us_w   = (const float*)d_in[8];
    const float* Us_b   = (const float*)d_in[9];
    const float* ma_w   = (const float*)d_in[10];
    const float* ma_b   = (const float*)d_in[11];
    const float* ilh_w  = (const float*)d_in[12];
    const float* ilh_b  = (const float*)d_in[13];
    const float* irh_w  = (const float*)d_in[14];
    const float* irh_b  = (const float*)d_in[15];
    const float* lflh_w = (const float*)d_in[16];
    const float* lflh_b = (const float*)d_in[17];
    const float* lfrh_w = (const float*)d_in[18];
    const float* lfrh_b = (const float*)d_in[19];
    const float* rflh_w = (const float*)d_in[20];
    const float* rflh_b = (const float*)d_in[21];
    const float* rfrh_w = (const float*)d_in[22];
    const float* rfrh_b = (const float*)d_in[23];
    const float* ulh_w  = (const float*)d_in[24];
    const float* ulh_b  = (const float*)d_in[25];
    const float* urh_w  = (const float*)d_in[26];
    const float* urh_b  = (const float*)d_in[27];

    float* out = (float*)d_out;

    k1_score<<<MEM / 4, 384>>>(lh, rh, S, w, Wh_w, Wh_b, Us_w, Us_b, ma_w);
    k2_alpha<<<1, 1024>>>(ma_b);
    k3_gates<<<MEM / 2, 512>>>(lc, rc,
                               ilh_w, ilh_b, irh_w, irh_b,
                               lflh_w, lflh_b, lfrh_w, lfrh_b,
                               rflh_w, rflh_b, rfrh_w, rfrh_b,
                               ulh_w, ulh_b, urh_w, urh_b,
                               out);
}

// round 4
// speedup vs baseline: 1.0943x; 1.0943x over previous
#include <cuda_runtime.h>
#include <math.h>

#define MEM 2048
#define NV4 (MEM / 4)          // float4 per row = 512

// Scratch (allocation-free: __device__ globals)
__device__ float g_sL[MEM];    // w[j] * m_left[j]
__device__ float g_sR[MEM];    // w[j] * m_right[j]
__device__ float g_pL[MEM];    // (ma @ lh)[j]
__device__ float g_pR[MEM];    // (ma @ rh)[j]
__device__ float g_la[MEM];
__device__ float g_ra[MEM];

__device__ __forceinline__ float warp_sum(float v) {
#pragma unroll
    for (int o = 16; o > 0; o >>= 1) v += __shfl_xor_sync(0xffffffffu, v, o);
    return v;
}

__device__ __forceinline__ float dot4(float4 a, float4 b) {
    return fmaf(a.x, b.x, fmaf(a.y, b.y, fmaf(a.z, b.z, a.w * b.w)));
}

// ---------------------------------------------------------------------------
// K1: attention scoring + hoisted ma matvecs.
// One BLOCK per output row j, 5 warps = one warp per dot product:
//   w0: Wh.lh   w1: Wh.rh   w2: Us.S   w3: ma.lh   w4: ma.rh
// Each warp streams one full matrix row (16 independent LDG.128, single
// stream) with the operand vector hitting L1 (8KB, reused across blocks).
// Wh/ma rows are read by two warps in the same block -> L1tex miss-merge
// dedupes the DRAM fetch.
// ---------------------------------------------------------------------------
__global__ void __launch_bounds__(160) k1_score(
    const float* __restrict__ lh, const float* __restrict__ rh,
    const float* __restrict__ S,  const float* __restrict__ w,
    const float* __restrict__ Wh_w, const float* __restrict__ Wh_b,
    const float* __restrict__ Us_w, const float* __restrict__ Us_b,
    const float* __restrict__ ma_w)
{
    const int row  = blockIdx.x;
    const int wid  = threadIdx.x >> 5;   // 0..4
    const int lane = threadIdx.x & 31;

    __shared__ float s_res[5];

    const size_t roff = (size_t)row * NV4;
    const float4* __restrict__ M;
    const float4* __restrict__ V;
    switch (wid) {
        case 0: M = (const float4*)Wh_w + roff; V = (const float4*)lh; break;
        case 1: M = (const float4*)Wh_w + roff; V = (const float4*)rh; break;
        case 2: M = (const float4*)Us_w + roff; V = (const float4*)S;  break;
        case 3: M = (const float4*)ma_w + roff; V = (const float4*)lh; break;
        default: M = (const float4*)ma_w + roff; V = (const float4*)rh; break;
    }

    float acc = 0.f;
#pragma unroll 8
    for (int i = 0; i < 16; i++) {
        const int idx = i * 32 + lane;
        acc += dot4(M[idx], V[idx]);
    }
    acc = warp_sum(acc);
    if (lane == 0) s_res[wid] = acc;
    __syncthreads();

    if (threadIdx.x == 0) {
        const float base = Wh_b[row] + Us_b[row];
        const float aUS  = s_res[2];
        const float mL = tanhf(s_res[0] + aUS + base);
        const float mR = tanhf(s_res[1] + aUS + base);
        const float wj = w[row];
        g_sL[row] = wj * mL;
        g_sR[row] = wj * mR;
        g_pL[row] = s_res[3];
        g_pR[row] = s_res[4];
    }
}

// ---------------------------------------------------------------------------
// K2: reduce scores -> alphas -> la/ra. Single block (tiny).
// ---------------------------------------------------------------------------
__global__ void __launch_bounds__(1024) k2_alpha(const float* __restrict__ ma_b)
{
    __shared__ float sL[1024];
    __shared__ float sR[1024];
    __shared__ float s_aL, s_aR;
    const int t = threadIdx.x;

    sL[t] = g_sL[t] + g_sL[t + 1024];
    sR[t] = g_sR[t] + g_sR[t + 1024];
    __syncthreads();
#pragma unroll
    for (int s = 512; s > 0; s >>= 1) {
        if (t < s) { sL[t] += sL[t + s]; sR[t] += sR[t + s]; }
        __syncthreads();
    }
    if (t == 0) {
        const float eL = sL[0], eR = sR[0];
        const float inv = 1.0f / (eL + eR);
        s_aL = eL * inv;
        s_aR = eR * inv;
    }
    __syncthreads();
    const float aL = s_aL, aR = s_aR;

#pragma unroll
    for (int j = t; j < MEM; j += 1024) {
        const float b = ma_b[j];
        g_la[j] = tanhf(fmaf(aL, g_pL[j], b));
        g_ra[j] = tanhf(fmaf(aR, g_pR[j], b));
    }
}

// ---------------------------------------------------------------------------
// K3: all 8 gate matvecs + LSTM combine.
// One BLOCK per output element j, 8 warps: one warp per gate matrix.
// Even warps dot with la, odd warps dot with ra (L1-resident vectors).
// ---------------------------------------------------------------------------
__global__ void __launch_bounds__(256) k3_gates(
    const float* __restrict__ lc, const float* __restrict__ rc,
    const float* __restrict__ ilh_w,  const float* __restrict__ ilh_b,
    const float* __restrict__ irh_w,  const float* __restrict__ irh_b,
    const float* __restrict__ lflh_w, const float* __restrict__ lflh_b,
    const float* __restrict__ lfrh_w, const float* __restrict__ lfrh_b,
    const float* __restrict__ rflh_w, const float* __restrict__ rflh_b,
    const float* __restrict__ rfrh_w, const float* __restrict__ rfrh_b,
    const float* __restrict__ ulh_w,  const float* __restrict__ ulh_b,
    const float* __restrict__ urh_w,  const float* __restrict__ urh_b,
    float* __restrict__ out)
{
    const int row  = blockIdx.x;
    const int wid  = threadIdx.x >> 5;   // 0..7 = gate index
    const int lane = threadIdx.x & 31;

    __shared__ float s_g[8];

    const float* mat;
    switch (wid) {
        case 0: mat = ilh_w;  break;
        case 1: mat = irh_w;  break;
        case 2: mat = lflh_w; break;
        case 3: mat = lfrh_w; break;
        case 4: mat = rflh_w; break;
        case 5: mat = rfrh_w; break;
        case 6: mat = ulh_w;  break;
        default: mat = urh_w; break;
    }
    const float4* __restrict__ M = (const float4*)mat + (size_t)row * NV4;
    const float4* __restrict__ V = (wid & 1) ? (const float4*)g_ra
                                             : (const float4*)g_la;

    float acc = 0.f;
#pragma unroll 8
    for (int i = 0; i < 16; i++) {
        const int idx = i * 32 + lane;
        acc += dot4(M[idx], V[idx]);
    }
    acc = warp_sum(acc);
    if (lane == 0) s_g[wid] = acc;
    __syncthreads();

    if (threadIdx.x == 0) {
        const int j = row;
        const float gi  = s_g[0] + s_g[1] + ilh_b[j]  + irh_b[j];
        const float glf = s_g[2] + s_g[3] + lflh_b[j] + lfrh_b[j];
        const float grf = s_g[4] + s_g[5] + rflh_b[j] + rfrh_b[j];
        const float gu  = s_g[6] + s_g[7] + ulh_b[j]  + urh_b[j];
        const float ig  = 1.0f / (1.0f + expf(-gi));
        const float lf  = 1.0f / (1.0f + expf(-glf));
        const float rf  = 1.0f / (1.0f + expf(-grf));
        const float u   = tanhf(gu);
        const float c   = ig * u + lf * lc[j] + rf * rc[j];
        out[j]       = c;
        out[MEM + j] = tanhf(c);
    }
}

// ---------------------------------------------------------------------------
// Input order (metadata): lc, lh, rc, rh, S, w, then (W, b) pairs for
// Wh, Us, ma, ilh, irh, lflh, lfrh, rflh, rfrh, ulh, urh.
// Output: c (2048 floats) followed by h (2048 floats).
// ---------------------------------------------------------------------------
extern "C" void kernel_launch(void* const* d_in, const int* in_sizes, int n_in,
                              void* d_out, int out_size)
{
    const float* lc = (const float*)d_in[0];
    const float* lh = (const float*)d_in[1];
    const float* rc = (const float*)d_in[2];
    const float* rh = (const float*)d_in[3];
    const float* S  = (const float*)d_in[4];
    const float* w  = (const float*)d_in[5];

    const float* Wh_w   = (const float*)d_in[6];
    const float* Wh_b   = (const float*)d_in[7];
    const float* Us_w   = (const float*)d_in[8];
    const float* Us_b   = (const float*)d_in[9];
    const float* ma_w   = (const float*)d_in[10];
    const float* ma_b   = (const float*)d_in[11];
    const float* ilh_w  = (const float*)d_in[12];
    const float* ilh_b  = (const float*)d_in[13];
    const float* irh_w  = (const float*)d_in[14];
    const float* irh_b  = (const float*)d_in[15];
    const float* lflh_w = (const float*)d_in[16];
    const float* lflh_b = (const float*)d_in[17];
    const float* lfrh_w = (const float*)d_in[18];
    const float* lfrh_b = (const float*)d_in[19];
    const float* rflh_w = (const float*)d_in[20];
    const float* rflh_b = (const float*)d_in[21];
    const float* rfrh_w = (const float*)d_in[22];
    const float* rfrh_b = (const float*)d_in[23];
    const float* ulh_w  = (const float*)d_in[24];
    const float* ulh_b  = (const float*)d_in[25];
    const float* urh_w  = (const float*)d_in[26];
    const float* urh_b  = (const float*)d_in[27];

    float* out = (float*)d_out;

    k1_score<<<MEM, 160>>>(lh, rh, S, w, Wh_w, Wh_b, Us_w, Us_b, ma_w);
    k2_alpha<<<1, 1024>>>(ma_b);
    k3_gates<<<MEM, 256>>>(lc, rc,
                           ilh_w, ilh_b, irh_w, irh_b,
                           lflh_w, lflh_b, lfrh_w, lfrh_b,
                           rflh_w, rflh_b, rfrh_w, rfrh_b,
                           ulh_w, ulh_b, urh_w, urh_b,
                           out);
}